// round 12
// baseline (speedup 1.0000x reference)
#include <cuda_runtime.h>
#include <cstdint>

#define NKEYS 50000
#define DDIM  64
#define NA    8
#define NB    256
#define KNN   50
#define DELTA 0.001f

// Fused GEMM+select tiling
#define BQ   64
#define BK   256
#define KTP  258      // padded row length for transposed K (floats)
#define NS   9        // n-splits
#define CH   5556     // keys per split (ceil(50000/9))

// Output offsets (float32 elements)
#define OFF_MAX   0
#define OFF_ACT   256
#define OFF_VALS  512
#define OFF_IDX   2560
#define OFF_SCORE 104960

// padding key: value +inf, max idx -> sorts after every real key
#define PADKEY ((0xFF800000ull << 32) | 0xFFFFFFFFull)

// Scratch (module-load allocation, allowed)
__device__ unsigned long long g_part[(size_t)NA * NB * NS * 64];  // 9.4 MB
__device__ float g_thr0[NA * NB];
__device__ float g_ksq[NA * NKEYS];
__device__ float g_qsq[NB];

// ---------------------------------------------------------------------------
// Reference-replica reduction (LLVM AArch64 NEON: VF=4, IC=2, faddp horiz).
// DO NOT TOUCH — bit-exactness verified in R8/R9.
// ---------------------------------------------------------------------------
__device__ __forceinline__ float reduce64_sq(const float* __restrict__ x) {
    float p0x=0.f,p0y=0.f,p0z=0.f,p0w=0.f;
    float p1x=0.f,p1y=0.f,p1z=0.f,p1w=0.f;
    #pragma unroll
    for (int i = 0; i < 8; i++) {
        float4 a = *(const float4*)(x + 8 * i);
        float4 b = *(const float4*)(x + 8 * i + 4);
        p0x = __fmaf_rn(a.x, a.x, p0x);
        p0y = __fmaf_rn(a.y, a.y, p0y);
        p0z = __fmaf_rn(a.z, a.z, p0z);
        p0w = __fmaf_rn(a.w, a.w, p0w);
        p1x = __fmaf_rn(b.x, b.x, p1x);
        p1y = __fmaf_rn(b.y, b.y, p1y);
        p1z = __fmaf_rn(b.z, b.z, p1z);
        p1w = __fmaf_rn(b.w, b.w, p1w);
    }
    float a0 = __fadd_rn(p0x, p1x);
    float a1 = __fadd_rn(p0y, p1y);
    float a2 = __fadd_rn(p0z, p1z);
    float a3 = __fadd_rn(p0w, p1w);
    return __fadd_rn(__fadd_rn(a0, a1), __fadd_rn(a2, a3));
}

__device__ __forceinline__ float reduce64_diff_sq(const float* __restrict__ q,
                                                  const float* __restrict__ k) {
    float p0[4] = {0.f,0.f,0.f,0.f};
    float p1[4] = {0.f,0.f,0.f,0.f};
    #pragma unroll
    for (int i = 0; i < 8; i++) {
        #pragma unroll
        for (int j = 0; j < 4; j++) {
            float d0 = __fsub_rn(q[8*i + j],     k[8*i + j]);
            float d1 = __fsub_rn(q[8*i + 4 + j], k[8*i + 4 + j]);
            p0[j] = __fmaf_rn(d0, d0, p0[j]);
            p1[j] = __fmaf_rn(d1, d1, p1[j]);
        }
    }
    float a0 = __fadd_rn(p0[0], p1[0]);
    float a1 = __fadd_rn(p0[1], p1[1]);
    float a2 = __fadd_rn(p0[2], p1[2]);
    float a3 = __fadd_rn(p0[3], p1[3]);
    return __fadd_rn(__fadd_rn(a0, a1), __fadd_rn(a2, a3));
}

// ---------------------------------------------------------------------------
__global__ void ksq_kernel(const float* __restrict__ keys) {
    int kk = blockIdx.x * 256 + threadIdx.x;
    if (kk >= NA * NKEYS) return;
    g_ksq[kk] = reduce64_sq(keys + (size_t)kk * DDIM);
}

__global__ void qsq_kernel(const float* __restrict__ q) {
    int b = threadIdx.x;
    g_qsq[b] = reduce64_sq(q + (size_t)b * DDIM);
}

// ---------------------------------------------------------------------------
__device__ __forceinline__ float unpack_key(unsigned long long e) {
    unsigned int u = (unsigned)(e >> 32);
    u = (u & 0x80000000u) ? (u & 0x7fffffffu) : ~u;
    return __uint_as_float(u);
}

// ---------------------------------------------------------------------------
// Seed: per (a,b), replica-exact d2 of first 512 keys; thr0 = 50th smallest.
// Valid filter bound: 50th of subset >= 50th of full set.
// Scalar fmaf chain == each f32x2 lane chain (same rounding).
// ---------------------------------------------------------------------------
__global__ void __launch_bounds__(256)
seed_kernel(const float* __restrict__ query, const float* __restrict__ keys) {
    __shared__ float sv[512];
    int t = threadIdx.x;
    int b = blockIdx.x, a = blockIdx.y;
    float qs = g_qsq[b];
    const float* qp = query + (size_t)b * DDIM;
    #pragma unroll
    for (int r = 0; r < 2; r++) {
        int n = t + 256 * r;
        const float* kp = keys + ((size_t)a * NKEYS + n) * DDIM;
        float acc = 0.f;
        #pragma unroll
        for (int k = 0; k < DDIM; k++) acc = __fmaf_rn(qp[k], __ldg(kp + k), acc);
        sv[n] = __fsub_rn(__fadd_rn(qs, g_ksq[a * NKEYS + n]), __fmul_rn(2.0f, acc));
    }
    __syncthreads();
    for (int k = 2; k <= 512; k <<= 1) {
        for (int j = k >> 1; j; j >>= 1) {
            #pragma unroll
            for (int r = 0; r < 2; r++) {
                int i = t + 256 * r, l = i ^ j;
                if (l > i) {
                    float x = sv[i], y = sv[l];
                    bool up = ((i & k) == 0);
                    if ((x > y) == up) { sv[i] = y; sv[l] = x; }
                }
            }
            __syncthreads();
        }
    }
    if (t == 0) g_thr0[a * NB + b] = sv[KNN - 1];
}

// ---------------------------------------------------------------------------
// Warp-scope compaction: sort staging (<=64), keep lowest 64 of (top U stg),
// tighten threshold to top[49]. Exact (value,idx) key order.
// Call sites guarantee cnt is warp-uniform.
// ---------------------------------------------------------------------------
__device__ __noinline__ void warp_compact(unsigned long long* top,
                                          unsigned long long* stg,
                                          int cnt, int lane, float* thrp) {
    #pragma unroll
    for (int r = 0; r < 2; r++) { int i = lane + 32*r; if (i >= cnt) stg[i] = PADKEY; }
    __syncwarp();
    for (int k = 2; k <= 64; k <<= 1) {
        for (int j = k >> 1; j; j >>= 1) {
            #pragma unroll
            for (int r = 0; r < 2; r++) {
                int i = lane + 32*r, l = i ^ j;
                if (l > i) {
                    unsigned long long x = stg[i], y = stg[l];
                    bool up = ((i & k) == 0);
                    if ((x > y) == up) { stg[i] = y; stg[l] = x; }
                }
            }
            __syncwarp();
        }
    }
    #pragma unroll
    for (int r = 0; r < 2; r++) {
        int i = lane + 32*r;
        unsigned long long x = top[i], y = stg[63 - i];
        top[i] = x < y ? x : y;
    }
    __syncwarp();
    for (int j = 32; j; j >>= 1) {
        #pragma unroll
        for (int r = 0; r < 2; r++) {
            int i = lane + 32*r, l = i ^ j;
            if (l > i) {
                unsigned long long x = top[i], y = top[l];
                if (x > y) { top[i] = y; top[l] = x; }
            }
        }
        __syncwarp();
    }
    if (lane == 0) *thrp = fminf(*thrp, unpack_key(top[KNN - 1]));
    __syncwarp();
}

// ---------------------------------------------------------------------------
// Fused distance-GEMM + per-query top-k. d2 arithmetic identical to R8/R9.
// Warp w owns q rows w*8..w*8+7: selection state is warp-private.
// ---------------------------------------------------------------------------
#define SM_QP    0
#define SM_KT    32768
#define SM_KS    (32768 + 66048)          // 98816
#define SM_QS    (SM_KS + 1024)           // 99840
#define SM_THR   (SM_QS + 256)            // 100096
#define SM_SCNT  (SM_THR + 256)           // 100352
#define SM_TOP   (SM_SCNT + 256)          // 100608 (8B aligned)
#define SM_STG   (SM_TOP + 32768)         // 133376
#define FUSED_SMEM (SM_STG + 32768)       // 166144

__global__ void __launch_bounds__(256, 1)
fused_kernel(const float* __restrict__ query, const float* __restrict__ keys) {
    extern __shared__ char smraw[];
    unsigned long long* Qp   = (unsigned long long*)(smraw + SM_QP);   // [BQ][DDIM] (q,q)
    float* Kt    = (float*)(smraw + SM_KT);                            // [DDIM][KTP]
    float* s_ks  = (float*)(smraw + SM_KS);                            // [BK]
    float* s_qs  = (float*)(smraw + SM_QS);                            // [BQ]
    float* s_thr = (float*)(smraw + SM_THR);                           // [BQ]
    int*   s_scnt = (int*)(smraw + SM_SCNT);                           // [BQ]
    unsigned long long* s_top = (unsigned long long*)(smraw + SM_TOP); // [BQ][64]
    unsigned long long* s_stg = (unsigned long long*)(smraw + SM_STG); // [BQ][64]

    int t = threadIdx.x;
    int split = blockIdx.x, bt = blockIdx.y, a = blockIdx.z;
    int nstart = split * CH;
    int nend   = min(nstart + CH, NKEYS);

    // stage Q packed (q,q) — once
    #pragma unroll
    for (int i = 0; i < 4; i++) {
        int f4 = t + 256 * i;
        int qi = f4 >> 4, dc = f4 & 15;
        float4 v = *(const float4*)(query + (size_t)(bt * BQ + qi) * DDIM + dc * 4);
        unsigned long long* dst = Qp + qi * DDIM + dc * 4;
        unsigned ux = __float_as_uint(v.x), uy = __float_as_uint(v.y);
        unsigned uz = __float_as_uint(v.z), uw = __float_as_uint(v.w);
        dst[0] = ((unsigned long long)ux << 32) | ux;
        dst[1] = ((unsigned long long)uy << 32) | uy;
        dst[2] = ((unsigned long long)uz << 32) | uz;
        dst[3] = ((unsigned long long)uw << 32) | uw;
    }
    // init selection state
    if (t < BQ) {
        s_qs[t]  = g_qsq[bt * BQ + t];
        s_thr[t] = g_thr0[a * NB + bt * BQ + t];
        s_scnt[t] = 0;
    }
    for (int i = t; i < BQ * 64; i += 256) s_top[i] = PADKEY;

    const float* kb = keys + (size_t)a * NKEYS * DDIM;
    int tx = t & 31, ty = t >> 5;
    int lane = tx;
    unsigned lmlt = (1u << lane) - 1u;
    const unsigned long long* qb = Qp + (ty * 8) * DDIM;

    for (int n0 = nstart; n0 < nend; n0 += BK) {
        __syncthreads();   // selection/epilogue of prev chunk done before restage
        // stage K transposed (zero-fill beyond nend) + ksq
        #pragma unroll
        for (int i = 0; i < 16; i++) {
            int f4 = t + 256 * i;
            int ki = f4 >> 4, dc = f4 & 15;
            int n = n0 + ki;
            float4 v = make_float4(0.f, 0.f, 0.f, 0.f);
            if (n < nend) v = __ldg((const float4*)(kb + (size_t)n * DDIM + dc * 4));
            Kt[(dc * 4 + 0) * KTP + ki] = v.x;
            Kt[(dc * 4 + 1) * KTP + ki] = v.y;
            Kt[(dc * 4 + 2) * KTP + ki] = v.z;
            Kt[(dc * 4 + 3) * KTP + ki] = v.w;
        }
        {
            int n = n0 + t;
            s_ks[t] = (n < nend) ? g_ksq[a * NKEYS + n] : 0.f;
        }
        __syncthreads();

        // mainloop — DO NOT TOUCH rounding: each 32-bit lane is the exact
        // sequential fp32 FMA chain over k (replica-verified)
        unsigned long long acc[8][4];
        #pragma unroll
        for (int i = 0; i < 8; i++)
            #pragma unroll
            for (int j = 0; j < 4; j++) acc[i][j] = 0ull;

        #pragma unroll 4
        for (int k = 0; k < DDIM; k++) {
            unsigned long long k2[4];
            const float* kr = Kt + k * KTP;
            #pragma unroll
            for (int j = 0; j < 4; j++)
                k2[j] = *(const unsigned long long*)(kr + 2 * (tx + 32 * j));
            unsigned long long q2[8];
            #pragma unroll
            for (int i = 0; i < 8; i++)
                q2[i] = qb[i * DDIM + k];
            #pragma unroll
            for (int i = 0; i < 8; i++)
                #pragma unroll
                for (int j = 0; j < 4; j++)
                    asm("fma.rn.f32x2 %0, %1, %2, %0;"
                        : "+l"(acc[i][j]) : "l"(q2[i]), "l"(k2[j]));
        }

        // epilogue: warp-private filtered append per q row
        #pragma unroll
        for (int i = 0; i < 8; i++) {
            int qloc = ty * 8 + i;
            float qs  = s_qs[qloc];
            float thr = s_thr[qloc];
            int   cnt = s_scnt[qloc];
            unsigned long long* top = s_top + qloc * 64;
            unsigned long long* stg = s_stg + qloc * 64;
            #pragma unroll
            for (int j = 0; j < 4; j++) {
                int nl = 2 * (tx + 32 * j);
                unsigned long long v = acc[i][j];
                #pragma unroll
                for (int c = 0; c < 2; c++) {
                    unsigned du = (c == 0) ? (unsigned)(v & 0xffffffffull)
                                           : (unsigned)(v >> 32);
                    float dot = __uint_as_float(du);
                    float ks  = s_ks[nl + c];
                    float d2  = __fsub_rn(__fadd_rn(qs, ks), __fmul_rn(2.0f, dot));
                    int n = n0 + nl + c;
                    bool pass = (n < nend) && (d2 <= thr);
                    unsigned m = __ballot_sync(0xffffffffu, pass);
                    if (pass) {
                        unsigned u = __float_as_uint(d2);
                        u = (u & 0x80000000u) ? ~u : (u | 0x80000000u);
                        stg[cnt + __popc(m & lmlt)] =
                            ((unsigned long long)u << 32) | (unsigned)n;
                    }
                    cnt += __popc(m);
                    if (cnt > 32) {          // staging can never exceed 64
                        warp_compact(top, stg, cnt, lane, s_thr + qloc);
                        cnt = 0;
                        thr = s_thr[qloc];
                    }
                }
            }
            s_scnt[qloc] = cnt;
        }
    }

    // flush + emit sorted top-64 per q
    #pragma unroll
    for (int i = 0; i < 8; i++) {
        int qloc = ty * 8 + i;
        int cnt = s_scnt[qloc];
        if (cnt > 0)
            warp_compact(s_top + qloc * 64, s_stg + qloc * 64, cnt, lane, s_thr + qloc);
        size_t pi = (size_t)a * NB + (bt * BQ + qloc);
        #pragma unroll
        for (int r = 0; r < 2; r++)
            g_part[(pi * NS + split) * 64 + lane + 32 * r] = s_top[qloc * 64 + lane + 32 * r];
    }
}

// ---------------------------------------------------------------------------
// Merge NS sorted top-64 lists per (a,b) -> exact global top-50; outputs.
// One warp per (a,b).
// ---------------------------------------------------------------------------
__global__ void __launch_bounds__(256)
merge_out_kernel(const float* __restrict__ query, const float* __restrict__ keys,
                 const float* __restrict__ vals, float* __restrict__ out) {
    __shared__ unsigned long long s_cur[8][64];
    __shared__ float s_w[8][64], s_wv[8][64];
    int t = threadIdx.x, wid = t >> 5, lane = t & 31;
    int p = blockIdx.x * 8 + wid;          // 0..2047 = a*NB + b
    int a = p / NB, b = p % NB;

    const unsigned long long* base = g_part + (size_t)p * NS * 64;
    #pragma unroll
    for (int r = 0; r < 2; r++)
        s_cur[wid][lane + 32 * r] = base[lane + 32 * r];
    __syncwarp();
    for (int s = 1; s < NS; s++) {
        const unsigned long long* nx = base + s * 64;
        #pragma unroll
        for (int r = 0; r < 2; r++) {
            int i = lane + 32 * r;
            unsigned long long x = s_cur[wid][i], y = nx[63 - i];
            s_cur[wid][i] = x < y ? x : y;
        }
        __syncwarp();
        for (int j = 32; j; j >>= 1) {
            #pragma unroll
            for (int r = 0; r < 2; r++) {
                int i = lane + 32 * r, l = i ^ j;
                if (l > i) {
                    unsigned long long x = s_cur[wid][i], y = s_cur[wid][l];
                    if (x > y) { s_cur[wid][i] = y; s_cur[wid][l] = x; }
                }
            }
            __syncwarp();
        }
    }

    // outputs: replica-exact recompute (reduce64_diff_sq), same as R9 tail
    const float* qp = query + (size_t)b * DDIM;
    #pragma unroll
    for (int r = 0; r < 2; r++) {
        int ni = lane + 32 * r;
        if (ni < KNN) {
            int idx = (int)(s_cur[wid][ni] & 0xffffffffull);
            const float* kp = keys + ((size_t)a * NKEYS + idx) * DDIM;
            float dist = reduce64_diff_sq(qp, kp);
            float w = 1.0f / (dist + DELTA);
            s_w[wid][ni]  = w;
            s_wv[wid][ni] = w * vals[(size_t)a * NKEYS + idx];
            out[OFF_IDX   + (b * NA + a) * KNN + ni] = (float)idx;
            out[OFF_SCORE + (b * NA + a) * KNN + ni] = dist;
        }
    }
    __syncwarp();
    if (lane == 0) {
        float sw = 0.f, swv = 0.f;
        for (int i = 0; i < KNN; i++) { sw += s_w[wid][i]; swv += s_wv[wid][i]; }
        out[OFF_VALS + b * NA + a] = swv / sw;
    }
}

// ---------------------------------------------------------------------------
__global__ void finalize_kernel(float* __restrict__ out) {
    int b = threadIdx.x;
    if (b < NB) {
        float best = out[OFF_VALS + b * NA];
        int arg = 0;
        #pragma unroll
        for (int a = 1; a < NA; a++) {
            float v = out[OFF_VALS + b * NA + a];
            if (v > best) { best = v; arg = a; }
        }
        out[OFF_MAX + b] = best;
        out[OFF_ACT + b] = (float)arg;
    }
}

// ---------------------------------------------------------------------------
extern "C" void kernel_launch(void* const* d_in, const int* in_sizes, int n_in,
                              void* d_out, int out_size) {
    const float* query = (const float*)d_in[0];
    const float* keys  = (const float*)d_in[1];
    const float* vals  = (const float*)d_in[2];
    float* out = (float*)d_out;

    cudaFuncSetAttribute(fused_kernel,
                         cudaFuncAttributeMaxDynamicSharedMemorySize, FUSED_SMEM);

    ksq_kernel<<<(NA * NKEYS + 255) / 256, 256>>>(keys);
    qsq_kernel<<<1, 256>>>(query);

    dim3 gseed(NB, NA);
    seed_kernel<<<gseed, 256>>>(query, keys);

    dim3 gf(NS, NB / BQ, NA);
    fused_kernel<<<gf, 256, FUSED_SMEM>>>(query, keys);

    merge_out_kernel<<<NA * NB / 8, 256>>>(query, keys, vals, out);

    finalize_kernel<<<1, 256>>>(out);
}

// round 13
// speedup vs baseline: 1.3903x; 1.3903x over previous
#include <cuda_runtime.h>
#include <cstdint>

#define NKEYS 50000
#define DDIM  64
#define NA    8
#define NB    256
#define KNN   50
#define DELTA 0.001f

// GEMM tiling
#define BQ   64
#define BK   256
#define KTP  258   // padded row length for transposed K (floats)

// Selection
#define NF4   (NKEYS / 4)                  // 12500
#define ITERS ((NF4 + 255) / 256)          // 49

// Output offsets (float32 elements)
#define OFF_MAX   0
#define OFF_ACT   256
#define OFF_VALS  512
#define OFF_IDX   2560
#define OFF_SCORE 104960

// padding key: value +inf, max idx -> sorts after every real key
#define PADKEY ((0xFF800000ull << 32) | 0xFFFFFFFFull)

// Scratch (module-load allocation, allowed)
__device__ float g_d2[(size_t)NA * NB * NKEYS];   // 409.6 MB
__device__ float g_ksq[NA * NKEYS];
__device__ float g_qsq[NB];

// ---------------------------------------------------------------------------
// Reference-replica reduction (LLVM AArch64 NEON: VF=4, IC=2, faddp horiz).
// DO NOT TOUCH — bit-exactness verified in R8/R9.
// ---------------------------------------------------------------------------
__device__ __forceinline__ float reduce64_sq(const float* __restrict__ x) {
    float p0x=0.f,p0y=0.f,p0z=0.f,p0w=0.f;
    float p1x=0.f,p1y=0.f,p1z=0.f,p1w=0.f;
    #pragma unroll
    for (int i = 0; i < 8; i++) {
        float4 a = *(const float4*)(x + 8 * i);
        float4 b = *(const float4*)(x + 8 * i + 4);
        p0x = __fmaf_rn(a.x, a.x, p0x);
        p0y = __fmaf_rn(a.y, a.y, p0y);
        p0z = __fmaf_rn(a.z, a.z, p0z);
        p0w = __fmaf_rn(a.w, a.w, p0w);
        p1x = __fmaf_rn(b.x, b.x, p1x);
        p1y = __fmaf_rn(b.y, b.y, p1y);
        p1z = __fmaf_rn(b.z, b.z, p1z);
        p1w = __fmaf_rn(b.w, b.w, p1w);
    }
    float a0 = __fadd_rn(p0x, p1x);
    float a1 = __fadd_rn(p0y, p1y);
    float a2 = __fadd_rn(p0z, p1z);
    float a3 = __fadd_rn(p0w, p1w);
    return __fadd_rn(__fadd_rn(a0, a1), __fadd_rn(a2, a3));
}

__device__ __forceinline__ float reduce64_diff_sq(const float* __restrict__ q,
                                                  const float* __restrict__ k) {
    float p0[4] = {0.f,0.f,0.f,0.f};
    float p1[4] = {0.f,0.f,0.f,0.f};
    #pragma unroll
    for (int i = 0; i < 8; i++) {
        #pragma unroll
        for (int j = 0; j < 4; j++) {
            float d0 = __fsub_rn(q[8*i + j],     k[8*i + j]);
            float d1 = __fsub_rn(q[8*i + 4 + j], k[8*i + 4 + j]);
            p0[j] = __fmaf_rn(d0, d0, p0[j]);
            p1[j] = __fmaf_rn(d1, d1, p1[j]);
        }
    }
    float a0 = __fadd_rn(p0[0], p1[0]);
    float a1 = __fadd_rn(p0[1], p1[1]);
    float a2 = __fadd_rn(p0[2], p1[2]);
    float a3 = __fadd_rn(p0[3], p1[3]);
    return __fadd_rn(__fadd_rn(a0, a1), __fadd_rn(a2, a3));
}

// ---------------------------------------------------------------------------
__global__ void ksq_kernel(const float* __restrict__ keys) {
    int kk = blockIdx.x * 256 + threadIdx.x;
    if (kk >= NA * NKEYS) return;
    g_ksq[kk] = reduce64_sq(keys + (size_t)kk * DDIM);
}

__global__ void qsq_kernel(const float* __restrict__ q) {
    int b = threadIdx.x;
    g_qsq[b] = reduce64_sq(q + (size_t)b * DDIM);
}

// ---------------------------------------------------------------------------
// Distance GEMM, reference-replica rounding (unchanged from R9 / validated).
// ---------------------------------------------------------------------------
__global__ void __launch_bounds__(256, 1)
gemm_kernel(const float* __restrict__ query, const float* __restrict__ keys) {
    extern __shared__ char smraw[];
    unsigned long long* Qp = (unsigned long long*)smraw;          // [BQ][DDIM] (q,q) pairs
    float* Kt = (float*)(smraw + BQ * DDIM * 8);                  // [DDIM][KTP]

    int t = threadIdx.x;
    int nt = blockIdx.x, bt = blockIdx.y, a = blockIdx.z;
    int n0 = nt * BK;

    #pragma unroll
    for (int i = 0; i < 4; i++) {
        int f4 = t + 256 * i;
        int qi = f4 >> 4, dc = f4 & 15;
        float4 v = *(const float4*)(query + (size_t)(bt * BQ + qi) * DDIM + dc * 4);
        unsigned long long* dst = Qp + qi * DDIM + dc * 4;
        unsigned ux = __float_as_uint(v.x), uy = __float_as_uint(v.y);
        unsigned uz = __float_as_uint(v.z), uw = __float_as_uint(v.w);
        dst[0] = ((unsigned long long)ux << 32) | ux;
        dst[1] = ((unsigned long long)uy << 32) | uy;
        dst[2] = ((unsigned long long)uz << 32) | uz;
        dst[3] = ((unsigned long long)uw << 32) | uw;
    }
    const float* kb = keys + (size_t)a * NKEYS * DDIM;
    #pragma unroll
    for (int i = 0; i < 16; i++) {
        int f4 = t + 256 * i;
        int ki = f4 >> 4, dc = f4 & 15;
        int n = n0 + ki;
        float4 v = make_float4(0.f, 0.f, 0.f, 0.f);
        if (n < NKEYS) v = *(const float4*)(kb + (size_t)n * DDIM + dc * 4);
        Kt[(dc * 4 + 0) * KTP + ki] = v.x;
        Kt[(dc * 4 + 1) * KTP + ki] = v.y;
        Kt[(dc * 4 + 2) * KTP + ki] = v.z;
        Kt[(dc * 4 + 3) * KTP + ki] = v.w;
    }
    __syncthreads();

    int tx = t & 31, ty = t >> 5;
    unsigned long long acc[8][4];
    #pragma unroll
    for (int i = 0; i < 8; i++)
        #pragma unroll
        for (int j = 0; j < 4; j++) acc[i][j] = 0ull;

    const unsigned long long* qb = Qp + (ty * 8) * DDIM;

    #pragma unroll 4
    for (int k = 0; k < DDIM; k++) {
        unsigned long long k2[4];
        const float* kr = Kt + k * KTP;
        #pragma unroll
        for (int j = 0; j < 4; j++)
            k2[j] = *(const unsigned long long*)(kr + 2 * (tx + 32 * j));
        unsigned long long q2[8];
        #pragma unroll
        for (int i = 0; i < 8; i++)
            q2[i] = qb[i * DDIM + k];
        #pragma unroll
        for (int i = 0; i < 8; i++)
            #pragma unroll
            for (int j = 0; j < 4; j++)
                asm("fma.rn.f32x2 %0, %1, %2, %0;"
                    : "+l"(acc[i][j]) : "l"(q2[i]), "l"(k2[j]));
    }

    #pragma unroll
    for (int j = 0; j < 4; j++) {
        int n = n0 + 2 * (tx + 32 * j);
        if (n >= NKEYS) continue;
        float2 ks2 = *(const float2*)(g_ksq + a * NKEYS + n);
        bool ok1 = (n + 1 < NKEYS);
        #pragma unroll
        for (int i = 0; i < 8; i++) {
            int b = bt * BQ + ty * 8 + i;
            float qs = g_qsq[b];
            unsigned long long v = acc[i][j];
            float lo = __uint_as_float((unsigned)(v & 0xffffffffull));
            float hi = __uint_as_float((unsigned)(v >> 32));
            float d0 = __fsub_rn(__fadd_rn(qs, ks2.x), __fmul_rn(2.0f, lo));
            float* orow = g_d2 + (size_t)(a * NB + b) * NKEYS;
            if (ok1) {
                float d1 = __fsub_rn(__fadd_rn(qs, ks2.y), __fmul_rn(2.0f, hi));
                __stcs((float2*)(orow + n), make_float2(d0, d1));
            } else {
                __stcs(orow + n, d0);
            }
        }
    }
}

// ---------------------------------------------------------------------------
__device__ __forceinline__ float unpack_key(unsigned long long e) {
    unsigned int u = (unsigned)(e >> 32);
    u = (u & 0x80000000u) ? (u & 0x7fffffffu) : ~u;
    return __uint_as_float(u);
}

// ---------------------------------------------------------------------------
// Warp-scope compaction: sort staging (<=64), keep lowest 64 of (top U stg).
// Exact (value,idx) key order. cnt is warp-uniform at all call sites.
// ---------------------------------------------------------------------------
__device__ __forceinline__ void warp_compact(unsigned long long* top,
                                             unsigned long long* stg,
                                             int cnt, int lane) {
    #pragma unroll
    for (int r = 0; r < 2; r++) { int i = lane + 32*r; if (i >= cnt) stg[i] = PADKEY; }
    __syncwarp();
    for (int k = 2; k <= 64; k <<= 1) {
        for (int j = k >> 1; j; j >>= 1) {
            #pragma unroll
            for (int r = 0; r < 2; r++) {
                int i = lane + 32*r, l = i ^ j;
                if (l > i) {
                    unsigned long long x = stg[i], y = stg[l];
                    bool up = ((i & k) == 0);
                    if ((x > y) == up) { stg[i] = y; stg[l] = x; }
                }
            }
            __syncwarp();
        }
    }
    #pragma unroll
    for (int r = 0; r < 2; r++) {
        int i = lane + 32*r;
        unsigned long long x = top[i], y = stg[63 - i];
        top[i] = x < y ? x : y;
    }
    __syncwarp();
    for (int j = 32; j; j >>= 1) {
        #pragma unroll
        for (int r = 0; r < 2; r++) {
            int i = lane + 32*r, l = i ^ j;
            if (l > i) {
                unsigned long long x = top[i], y = top[l];
                if (x > y) { top[i] = y; top[l] = x; }
            }
        }
        __syncwarp();
    }
}

// ---------------------------------------------------------------------------
// Warp-autonomous top-50 per (a,b): 8 warps stream disjoint coalesced stripes
// with private top-64 state; one block barrier; warp 0 tournament-merges.
// ---------------------------------------------------------------------------
__global__ void __launch_bounds__(256)
select_kernel(const float* __restrict__ query, const float* __restrict__ keys,
              const float* __restrict__ vals, float* __restrict__ out) {
    __shared__ unsigned long long s_top[8][64];
    __shared__ unsigned long long s_stg[8][64];
    __shared__ float qv[DDIM];
    __shared__ float s_w[64], s_wv[64];

    int t = threadIdx.x, w = t >> 5, lane = t & 31;
    int b = blockIdx.x, a = blockIdx.y;
    unsigned lmlt = (1u << lane) - 1u;

    if (t < DDIM) qv[t] = query[b * DDIM + t];
    #pragma unroll
    for (int r = 0; r < 2; r++) s_top[w][lane + 32 * r] = PADKEY;
    __syncwarp();

    const float4* row = (const float4*)(g_d2 + (size_t)(a * NB + b) * NKEYS);
    unsigned long long* top = s_top[w];
    unsigned long long* stg = s_stg[w];

    float thr = 3.4e38f;
    int cnt = 0;

    #pragma unroll 2
    for (int it = 0; it < ITERS; it++) {
        int f4i = it * 256 + w * 32 + lane;
        bool inb = f4i < NF4;
        float4 v = make_float4(3.4e38f, 3.4e38f, 3.4e38f, 3.4e38f);
        if (inb) v = __ldcs(&row[f4i]);
        int n = f4i * 4;
        float vv[4] = {v.x, v.y, v.z, v.w};
        #pragma unroll
        for (int c = 0; c < 4; c++) {
            bool pass = inb && (vv[c] <= thr);
            unsigned m = __ballot_sync(0xffffffffu, pass);
            if (pass) {
                unsigned u = __float_as_uint(vv[c]);
                u = (u & 0x80000000u) ? ~u : (u | 0x80000000u);
                stg[cnt + __popc(m & lmlt)] =
                    ((unsigned long long)u << 32) | (unsigned)(n + c);
            }
            cnt += __popc(m);
            if (cnt > 32) {              // staging max 32+32=64, never overflows
                warp_compact(top, stg, cnt, lane);
                cnt = 0;
                thr = unpack_key(top[KNN - 1]);
            }
        }
    }
    if (cnt > 0) warp_compact(top, stg, cnt, lane);
    __syncthreads();

    // warp 0: tournament-merge 8 sorted lists -> exact global top-64
    if (w == 0) {
        for (int s = 1; s < 8; s++) {
            #pragma unroll
            for (int r = 0; r < 2; r++) {
                int i = lane + 32 * r;
                unsigned long long x = s_top[0][i], y = s_top[s][63 - i];
                s_top[0][i] = x < y ? x : y;
            }
            __syncwarp();
            for (int j = 32; j; j >>= 1) {
                #pragma unroll
                for (int r = 0; r < 2; r++) {
                    int i = lane + 32 * r, l = i ^ j;
                    if (l > i) {
                        unsigned long long x = s_top[0][i], y = s_top[0][l];
                        if (x > y) { s_top[0][i] = y; s_top[0][l] = x; }
                    }
                }
                __syncwarp();
            }
        }

        // outputs: replica-exact recompute (reduce64_diff_sq), as in R9 tail
        #pragma unroll
        for (int r = 0; r < 2; r++) {
            int ni = lane + 32 * r;
            if (ni < KNN) {
                int idx = (int)(s_top[0][ni] & 0xffffffffull);
                const float* kp = keys + ((size_t)a * NKEYS + idx) * DDIM;
                float dist = reduce64_diff_sq(qv, kp);
                float wt = 1.0f / (dist + DELTA);
                s_w[ni]  = wt;
                s_wv[ni] = wt * vals[(size_t)a * NKEYS + idx];
                out[OFF_IDX   + (b * NA + a) * KNN + ni] = (float)idx;
                out[OFF_SCORE + (b * NA + a) * KNN + ni] = dist;
            }
        }
        __syncwarp();
        if (lane == 0) {
            float sw = 0.f, swv = 0.f;
            for (int i = 0; i < KNN; i++) { sw += s_w[i]; swv += s_wv[i]; }
            out[OFF_VALS + b * NA + a] = swv / sw;
        }
    }
}

// ---------------------------------------------------------------------------
__global__ void finalize_kernel(float* __restrict__ out) {
    int b = threadIdx.x;
    if (b < NB) {
        float best = out[OFF_VALS + b * NA];
        int arg = 0;
        #pragma unroll
        for (int a = 1; a < NA; a++) {
            float v = out[OFF_VALS + b * NA + a];
            if (v > best) { best = v; arg = a; }
        }
        out[OFF_MAX + b] = best;
        out[OFF_ACT + b] = (float)arg;
    }
}

// ---------------------------------------------------------------------------
extern "C" void kernel_launch(void* const* d_in, const int* in_sizes, int n_in,
                              void* d_out, int out_size) {
    const float* query = (const float*)d_in[0];
    const float* keys  = (const float*)d_in[1];
    const float* vals  = (const float*)d_in[2];
    float* out = (float*)d_out;

    const int gemm_smem = BQ * DDIM * 8 + DDIM * KTP * 4;  // 98816 B
    cudaFuncSetAttribute(gemm_kernel,
                         cudaFuncAttributeMaxDynamicSharedMemorySize, gemm_smem);

    ksq_kernel<<<(NA * NKEYS + 255) / 256, 256>>>(keys);
    qsq_kernel<<<1, 256>>>(query);

    dim3 gg((NKEYS + BK - 1) / BK, NB / BQ, NA);
    gemm_kernel<<<gg, 256, gemm_smem>>>(query, keys);

    dim3 gs(NB, NA);
    select_kernel<<<gs, 256>>>(query, keys, vals, out);

    finalize_kernel<<<1, 256>>>(out);
}

// round 15
// speedup vs baseline: 2.3673x; 1.7027x over previous
#include <cuda_runtime.h>
#include <cstdint>

#define NKEYS 50000
#define DDIM  64
#define NA    8
#define NB    256
#define KNN   50
#define DELTA 0.001f

// GEMM tiling
#define BQ   64
#define BK   256
#define KTP  258   // padded row length for transposed K (floats)

// Selection
#define SCHUNK 4096
#define STG    4160

// Output offsets (float32 elements)
#define OFF_MAX   0
#define OFF_ACT   256
#define OFF_VALS  512
#define OFF_IDX   2560
#define OFF_SCORE 104960

// padding key: value +inf, max idx -> sorts after every real key
#define PADKEY ((0xFF800000ull << 32) | 0xFFFFFFFFull)

// Scratch (module-load allocation, allowed)
__device__ float g_d2[(size_t)NA * NB * NKEYS];   // 409.6 MB
__device__ float g_ksq[NA * NKEYS];
__device__ float g_qsq[NB];

// ---------------------------------------------------------------------------
// Reference-replica reduction (LLVM AArch64 NEON: VF=4, IC=2, faddp horiz).
// DO NOT TOUCH — bit-exactness verified in R8/R9.
// ---------------------------------------------------------------------------
__device__ __forceinline__ float reduce64_sq(const float* __restrict__ x) {
    float p0x=0.f,p0y=0.f,p0z=0.f,p0w=0.f;
    float p1x=0.f,p1y=0.f,p1z=0.f,p1w=0.f;
    #pragma unroll
    for (int i = 0; i < 8; i++) {
        float4 a = *(const float4*)(x + 8 * i);
        float4 b = *(const float4*)(x + 8 * i + 4);
        p0x = __fmaf_rn(a.x, a.x, p0x);
        p0y = __fmaf_rn(a.y, a.y, p0y);
        p0z = __fmaf_rn(a.z, a.z, p0z);
        p0w = __fmaf_rn(a.w, a.w, p0w);
        p1x = __fmaf_rn(b.x, b.x, p1x);
        p1y = __fmaf_rn(b.y, b.y, p1y);
        p1z = __fmaf_rn(b.z, b.z, p1z);
        p1w = __fmaf_rn(b.w, b.w, p1w);
    }
    float a0 = __fadd_rn(p0x, p1x);
    float a1 = __fadd_rn(p0y, p1y);
    float a2 = __fadd_rn(p0z, p1z);
    float a3 = __fadd_rn(p0w, p1w);
    return __fadd_rn(__fadd_rn(a0, a1), __fadd_rn(a2, a3));
}

__device__ __forceinline__ float reduce64_diff_sq(const float* __restrict__ q,
                                                  const float* __restrict__ k) {
    float p0[4] = {0.f,0.f,0.f,0.f};
    float p1[4] = {0.f,0.f,0.f,0.f};
    #pragma unroll
    for (int i = 0; i < 8; i++) {
        #pragma unroll
        for (int j = 0; j < 4; j++) {
            float d0 = __fsub_rn(q[8*i + j],     k[8*i + j]);
            float d1 = __fsub_rn(q[8*i + 4 + j], k[8*i + 4 + j]);
            p0[j] = __fmaf_rn(d0, d0, p0[j]);
            p1[j] = __fmaf_rn(d1, d1, p1[j]);
        }
    }
    float a0 = __fadd_rn(p0[0], p1[0]);
    float a1 = __fadd_rn(p0[1], p1[1]);
    float a2 = __fadd_rn(p0[2], p1[2]);
    float a3 = __fadd_rn(p0[3], p1[3]);
    return __fadd_rn(__fadd_rn(a0, a1), __fadd_rn(a2, a3));
}

// ---------------------------------------------------------------------------
__global__ void ksq_kernel(const float* __restrict__ keys) {
    int kk = blockIdx.x * 256 + threadIdx.x;
    if (kk >= NA * NKEYS) return;
    g_ksq[kk] = reduce64_sq(keys + (size_t)kk * DDIM);
}

__global__ void qsq_kernel(const float* __restrict__ q) {
    int b = threadIdx.x;
    g_qsq[b] = reduce64_sq(q + (size_t)b * DDIM);
}

// ---------------------------------------------------------------------------
// Distance GEMM, reference-replica rounding. 2 CTAs/SM so staging and
// epilogue of one CTA overlap the mainloop of the other.
// ---------------------------------------------------------------------------
__global__ void __launch_bounds__(256, 2)
gemm_kernel(const float* __restrict__ query, const float* __restrict__ keys) {
    extern __shared__ char smraw[];
    unsigned long long* Qp = (unsigned long long*)smraw;          // [BQ][DDIM] (q,q) pairs
    float* Kt = (float*)(smraw + BQ * DDIM * 8);                  // [DDIM][KTP]

    int t = threadIdx.x;
    int nt = blockIdx.x, bt = blockIdx.y, a = blockIdx.z;
    int n0 = nt * BK;

    #pragma unroll
    for (int i = 0; i < 4; i++) {
        int f4 = t + 256 * i;
        int qi = f4 >> 4, dc = f4 & 15;
        float4 v = *(const float4*)(query + (size_t)(bt * BQ + qi) * DDIM + dc * 4);
        unsigned long long* dst = Qp + qi * DDIM + dc * 4;
        unsigned ux = __float_as_uint(v.x), uy = __float_as_uint(v.y);
        unsigned uz = __float_as_uint(v.z), uw = __float_as_uint(v.w);
        dst[0] = ((unsigned long long)ux << 32) | ux;
        dst[1] = ((unsigned long long)uy << 32) | uy;
        dst[2] = ((unsigned long long)uz << 32) | uz;
        dst[3] = ((unsigned long long)uw << 32) | uw;
    }
    const float* kb = keys + (size_t)a * NKEYS * DDIM;
    #pragma unroll
    for (int i = 0; i < 16; i++) {
        int f4 = t + 256 * i;
        int ki = f4 >> 4, dc = f4 & 15;
        int n = n0 + ki;
        float4 v = make_float4(0.f, 0.f, 0.f, 0.f);
        if (n < NKEYS) v = *(const float4*)(kb + (size_t)n * DDIM + dc * 4);
        Kt[(dc * 4 + 0) * KTP + ki] = v.x;
        Kt[(dc * 4 + 1) * KTP + ki] = v.y;
        Kt[(dc * 4 + 2) * KTP + ki] = v.z;
        Kt[(dc * 4 + 3) * KTP + ki] = v.w;
    }
    __syncthreads();

    int tx = t & 31, ty = t >> 5;
    unsigned long long acc[8][4];
    #pragma unroll
    for (int i = 0; i < 8; i++)
        #pragma unroll
        for (int j = 0; j < 4; j++) acc[i][j] = 0ull;

    const unsigned long long* qb = Qp + (ty * 8) * DDIM;

    #pragma unroll 4
    for (int k = 0; k < DDIM; k++) {
        unsigned long long k2[4];
        const float* kr = Kt + k * KTP;
        #pragma unroll
        for (int j = 0; j < 4; j++)
            k2[j] = *(const unsigned long long*)(kr + 2 * (tx + 32 * j));
        unsigned long long q2[8];
        #pragma unroll
        for (int i = 0; i < 8; i++)
            q2[i] = qb[i * DDIM + k];
        #pragma unroll
        for (int i = 0; i < 8; i++)
            #pragma unroll
            for (int j = 0; j < 4; j++)
                asm("fma.rn.f32x2 %0, %1, %2, %0;"
                    : "+l"(acc[i][j]) : "l"(q2[i]), "l"(k2[j]));
    }

    #pragma unroll
    for (int j = 0; j < 4; j++) {
        int n = n0 + 2 * (tx + 32 * j);
        if (n >= NKEYS) continue;
        float2 ks2 = *(const float2*)(g_ksq + a * NKEYS + n);
        bool ok1 = (n + 1 < NKEYS);
        #pragma unroll
        for (int i = 0; i < 8; i++) {
            int b = bt * BQ + ty * 8 + i;
            float qs = g_qsq[b];
            unsigned long long v = acc[i][j];
            float lo = __uint_as_float((unsigned)(v & 0xffffffffull));
            float hi = __uint_as_float((unsigned)(v >> 32));
            float d0 = __fsub_rn(__fadd_rn(qs, ks2.x), __fmul_rn(2.0f, lo));
            float* orow = g_d2 + (size_t)(a * NB + b) * NKEYS;
            if (ok1) {
                float d1 = __fsub_rn(__fadd_rn(qs, ks2.y), __fmul_rn(2.0f, hi));
                __stcs((float2*)(orow + n), make_float2(d0, d1));
            } else {
                __stcs(orow + n, d0);
            }
        }
    }
}

// ---------------------------------------------------------------------------
__device__ __forceinline__ float unpack_key(unsigned long long e) {
    unsigned int u = (unsigned)(e >> 32);
    u = (u & 0x80000000u) ? (u & 0x7fffffffu) : ~u;
    return __uint_as_float(u);
}

// ---------------------------------------------------------------------------
// Top-50 per (a,b): incremental sorted top-64 (R9-proven), wider chunks for
// MLP=4 and 4x fewer barriers.
// ---------------------------------------------------------------------------
__global__ void __launch_bounds__(256)
select_kernel(const float* __restrict__ query, const float* __restrict__ keys,
              const float* __restrict__ vals, float* __restrict__ out) {
    __shared__ unsigned long long s_top[64];
    __shared__ unsigned long long s_stg[STG];
    __shared__ unsigned long long s_mrg[64];
    __shared__ float s_mins[256];
    __shared__ int   s_cnt;
    __shared__ float s_thr;
    __shared__ float qv[DDIM];
    __shared__ float s_w[KNN], s_wv[KNN];

    int t = threadIdx.x;
    int b = blockIdx.x, a = blockIdx.y;

    if (t < DDIM) qv[t] = query[b * DDIM + t];
    if (t < 64)   s_top[t] = PADKEY;
    if (t == 0)   s_cnt = 0;

    const float4* row = (const float4*)(g_d2 + (size_t)(a * NB + b) * NKEYS);
    const int NF4 = NKEYS / 4;  // 12500

    // chunk-0 prefilter: 50th smallest of 256 per-thread mins (4 elems each).
    // Guarantees >=50 chunk-0 elements pass; expected ~55 pass.
    {
        float4 v = __ldcs(&row[t]);
        float m0 = fminf(fminf(v.x, v.y), fminf(v.z, v.w));
        s_mins[t] = m0;
        __syncthreads();
        for (int k = 2; k <= 256; k <<= 1) {
            for (int j = k >> 1; j > 0; j >>= 1) {
                int i = t, l = i ^ j;
                if (l > i) {
                    float x = s_mins[i], y = s_mins[l];
                    bool up = ((i & k) == 0);
                    if ((x > y) == up) { s_mins[i] = y; s_mins[l] = x; }
                }
                __syncthreads();
            }
        }
        if (t == 0) s_thr = s_mins[KNN - 1];
        __syncthreads();
    }

    for (int base = 0; base < NKEYS; base += SCHUNK) {
        float thr = s_thr;
        int f0 = base >> 2;
        #pragma unroll
        for (int j = 0; j < 4; j++) {
            int f4i = f0 + t + 256 * j;
            if (f4i < NF4) {
                float4 v = __ldcs(&row[f4i]);
                int n = f4i * 4;
                float vv[4] = {v.x, v.y, v.z, v.w};
                #pragma unroll
                for (int c = 0; c < 4; c++) {
                    if (vv[c] <= thr) {
                        int pos = atomicAdd(&s_cnt, 1);
                        unsigned int u = __float_as_uint(vv[c]);
                        u = (u & 0x80000000u) ? ~u : (u | 0x80000000u);
                        if (pos < STG)
                            s_stg[pos] = ((unsigned long long)u << 32) | (unsigned)(n + c);
                    }
                }
            }
        }
        __syncthreads();

        // drain staging in 64-wide merges
        for (;;) {
            int cnt = s_cnt;
            if (cnt <= 0) break;
            if (cnt > STG) cnt = STG;           // defensive (max 4096 appends/chunk)
            int m = cnt < 64 ? cnt : 64;
            if (t < 64) s_mrg[t] = (t < m) ? s_stg[cnt - m + t] : PADKEY;
            __syncthreads();
            // bitonic sort-64 ascending
            for (int k = 2; k <= 64; k <<= 1) {
                for (int j = k >> 1; j; j >>= 1) {
                    if (t < 64) {
                        int i = t, l = i ^ j;
                        if (l > i) {
                            unsigned long long x = s_mrg[i], y = s_mrg[l];
                            bool up = ((i & k) == 0);
                            if ((x > y) == up) { s_mrg[i] = y; s_mrg[l] = x; }
                        }
                    }
                    __syncthreads();
                }
            }
            // keep lowest 64 of (top, mrg): reversed min-CE -> bitonic cleanup
            if (t < 64) {
                unsigned long long x = s_top[t], y = s_mrg[63 - t];
                s_top[t] = x < y ? x : y;
            }
            __syncthreads();
            for (int j = 32; j; j >>= 1) {
                if (t < 64) {
                    int i = t, l = i ^ j;
                    if (l > i) {
                        unsigned long long x = s_top[i], y = s_top[l];
                        if (x > y) { s_top[i] = y; s_top[l] = x; }
                    }
                }
                __syncthreads();
            }
            if (t == 0) {
                s_cnt = cnt - m;
                s_thr = unpack_key(s_top[KNN - 1]);
            }
            __syncthreads();
        }
    }

    // outputs: s_top[0..49] is the exact sorted top-50
    if (t < KNN) {
        int idx = (int)(s_top[t] & 0xffffffffull);
        const float* kp = keys + ((size_t)a * NKEYS + idx) * DDIM;
        float dist = reduce64_diff_sq(qv, kp);
        float w = 1.0f / (dist + DELTA);
        s_w[t]  = w;
        s_wv[t] = w * vals[(size_t)a * NKEYS + idx];
        out[OFF_IDX   + (b * NA + a) * KNN + t] = (float)idx;
        out[OFF_SCORE + (b * NA + a) * KNN + t] = dist;
    }
    __syncthreads();
    if (t == 0) {
        float sw = 0.f, swv = 0.f;
        for (int i = 0; i < KNN; i++) { sw += s_w[i]; swv += s_wv[i]; }
        out[OFF_VALS + b * NA + a] = swv / sw;
    }
}

// ---------------------------------------------------------------------------
__global__ void finalize_kernel(float* __restrict__ out) {
    int b = threadIdx.x;
    if (b < NB) {
        float best = out[OFF_VALS + b * NA];
        int arg = 0;
        #pragma unroll
        for (int a = 1; a < NA; a++) {
            float v = out[OFF_VALS + b * NA + a];
            if (v > best) { best = v; arg = a; }
        }
        out[OFF_MAX + b] = best;
        out[OFF_ACT + b] = (float)arg;
    }
}

// ---------------------------------------------------------------------------
extern "C" void kernel_launch(void* const* d_in, const int* in_sizes, int n_in,
                              void* d_out, int out_size) {
    const float* query = (const float*)d_in[0];
    const float* keys  = (const float*)d_in[1];
    const float* vals  = (const float*)d_in[2];
    float* out = (float*)d_out;

    const int gemm_smem = BQ * DDIM * 8 + DDIM * KTP * 4;  // 98816 B
    cudaFuncSetAttribute(gemm_kernel,
                         cudaFuncAttributeMaxDynamicSharedMemorySize, gemm_smem);

    ksq_kernel<<<(NA * NKEYS + 255) / 256, 256>>>(keys);
    qsq_kernel<<<1, 256>>>(query);

    dim3 gg((NKEYS + BK - 1) / BK, NB / BQ, NA);
    gemm_kernel<<<gg, 256, gemm_smem>>>(query, keys);

    dim3 gs(NB, NA);
    select_kernel<<<gs, 256>>>(query, keys, vals, out);

    finalize_kernel<<<1, 256>>>(out);
}